// round 4
// baseline (speedup 1.0000x reference)
#include <cuda_runtime.h>

// Composite 13-tap kernel: C[n] = sum_{i+j=n} fd[i] * gauss[j]
__device__ float g_comb[13];

__global__ void build_comb_kernel(const float* __restrict__ fd,
                                  const float* __restrict__ gs) {
    int n = threadIdx.x;
    if (n < 13) {
        float s = 0.0f;
        #pragma unroll
        for (int i = 0; i < 5; i++) {
            int j = n - i;
            if (j >= 0 && j < 9) s += fd[i] * gs[j];
        }
        g_comb[n] = s;
    }
}

static constexpr int T_IN      = 1048576;
static constexpr int T_OUT     = T_IN - 12;       // 1048564
static constexpr int VEC_OUT   = T_OUT / 4;       // 262141 float4 outputs per row
static constexpr int VEC_IN    = T_IN / 4;        // 262144 float4 per input row
static constexpr int ROWS      = 32;              // 8 * 4
static constexpr int BLOCK     = 256;

__global__ __launch_bounds__(BLOCK)
void conv13_kernel(const float4* __restrict__ x, float4* __restrict__ out) {
    __shared__ float c[13];
    int tid = threadIdx.x;
    if (tid < 13) c[tid] = g_comb[tid];
    __syncthreads();

    int v = blockIdx.x * BLOCK + tid;
    if (v >= VEC_OUT) return;
    int row = blockIdx.y;

    const float4* xr = x + (size_t)row * VEC_IN;
    float4 a0 = xr[v];
    float4 a1 = xr[v + 1];
    float4 a2 = xr[v + 2];
    float4 a3 = xr[v + 3];

    float xs[16] = {a0.x, a0.y, a0.z, a0.w,
                    a1.x, a1.y, a1.z, a1.w,
                    a2.x, a2.y, a2.z, a2.w,
                    a3.x, a3.y, a3.z, a3.w};

    float cc[13];
    #pragma unroll
    for (int k = 0; k < 13; k++) cc[k] = c[k];

    float o[4];
    #pragma unroll
    for (int j = 0; j < 4; j++) {
        float s = 0.0f;
        #pragma unroll
        for (int k = 0; k < 13; k++) s = fmaf(cc[k], xs[j + k], s);
        o[j] = s;
    }

    out[(size_t)row * VEC_OUT + v] = make_float4(o[0], o[1], o[2], o[3]);
}

extern "C" void kernel_launch(void* const* d_in, const int* in_sizes, int n_in,
                              void* d_out, int out_size) {
    const float* x  = (const float*)d_in[0];
    const float* fd = (const float*)d_in[1];
    const float* gs = (const float*)d_in[2];
    float* out = (float*)d_out;

    build_comb_kernel<<<1, 32>>>(fd, gs);

    dim3 grid((VEC_OUT + BLOCK - 1) / BLOCK, ROWS);
    conv13_kernel<<<grid, BLOCK>>>((const float4*)x, (float4*)out);
}

// round 7
// speedup vs baseline: 1.0951x; 1.0951x over previous
#include <cuda_runtime.h>

static constexpr int T_IN    = 1048576;
static constexpr int T_OUT   = T_IN - 12;         // 1048564
static constexpr int VEC_OUT = T_OUT / 4;         // 262141 output float4 per row
static constexpr int VEC_IN  = T_IN / 4;          // 262144 input float4 per row
static constexpr int ROWS    = 32;                // 8 * 4
static constexpr int BLOCK   = 256;
static constexpr int WARPS   = BLOCK / 32;        // 8
static constexpr int STEPS   = 4;                 // 32-vec windows per warp run
static constexpr int RUN     = 32 * STEPS;        // 128 outvecs per warp
static constexpr int RUNS_PER_ROW = (VEC_OUT + RUN - 1) / RUN;  // 2048
static constexpr int BLOCKS_X     = RUNS_PER_ROW / WARPS;       // 256

__global__ __launch_bounds__(BLOCK)
void conv13_shfl(const float4* __restrict__ x, float4* __restrict__ out,
                 const float* __restrict__ fd, const float* __restrict__ gs) {
    // Build composite 13-tap kernel per block (folds the old setup launch).
    __shared__ float csm[13];
    int tid = threadIdx.x;
    if (tid < 13) {
        float s = 0.0f;
        #pragma unroll
        for (int i = 0; i < 5; i++) {
            int j = tid - i;
            if (j >= 0 && j < 9) s += fd[i] * gs[j];
        }
        csm[tid] = s;
    }
    __syncthreads();

    const int lane = tid & 31;
    const int warp = tid >> 5;
    const int row  = blockIdx.y;
    const int B    = (blockIdx.x * WARPS + warp) * RUN;  // first outvec of this warp's run

    const float4* __restrict__ xr = x + (size_t)row * VEC_IN;
    float4* __restrict__ orow     = out + (size_t)row * VEC_OUT;

    float cc[13];
    #pragma unroll
    for (int k = 0; k < 13; k++) cc[k] = csm[k];

    // Front-batched loads: one float4 per lane per 32-vec window, plus one halo window.
    float4 w[STEPS + 1];
    #pragma unroll
    for (int i = 0; i <= STEPS; i++) {
        int idx = B + i * 32 + lane;
        idx = min(idx, VEC_IN - 1);   // clamp only matters in last run; guarded outputs
        w[i] = xr[idx];
    }

    #pragma unroll
    for (int s = 0; s < STEPS; s++) {
        float xs[16];
        xs[0] = w[s].x; xs[1] = w[s].y; xs[2] = w[s].z; xs[3] = w[s].w;

        // Neighbor windows k=1..3 via select-before-shuffle:
        // source lane sl=(lane+k)&31 is read by exactly one reader; reader wants
        // next-window data iff sl < k, so the select can be done at the source.
        #pragma unroll
        for (int k = 1; k <= 3; k++) {
            float mx = (lane < k) ? w[s + 1].x : w[s].x;
            float my = (lane < k) ? w[s + 1].y : w[s].y;
            float mz = (lane < k) ? w[s + 1].z : w[s].z;
            float mw = (lane < k) ? w[s + 1].w : w[s].w;
            int src = (lane + k) & 31;
            xs[4 * k + 0] = __shfl_sync(0xffffffffu, mx, src);
            xs[4 * k + 1] = __shfl_sync(0xffffffffu, my, src);
            xs[4 * k + 2] = __shfl_sync(0xffffffffu, mz, src);
            xs[4 * k + 3] = __shfl_sync(0xffffffffu, mw, src);
        }

        float o[4];
        #pragma unroll
        for (int j = 0; j < 4; j++) {
            float acc = 0.0f;
            #pragma unroll
            for (int k = 0; k < 13; k++) acc = fmaf(cc[k], xs[j + k], acc);
            o[j] = acc;
        }

        int v = B + s * 32 + lane;
        if (v < VEC_OUT) orow[v] = make_float4(o[0], o[1], o[2], o[3]);
    }
}

extern "C" void kernel_launch(void* const* d_in, const int* in_sizes, int n_in,
                              void* d_out, int out_size) {
    const float* x  = (const float*)d_in[0];
    const float* fd = (const float*)d_in[1];
    const float* gs = (const float*)d_in[2];
    float* out = (float*)d_out;

    dim3 grid(BLOCKS_X, ROWS);
    conv13_shfl<<<grid, BLOCK>>>((const float4*)x, (float4*)out, fd, gs);
}